// round 3
// baseline (speedup 1.0000x reference)
#include <cuda_runtime.h>

// DEQSolver closed form: out[i] = sign(x[i]) * max(|x[i]| - lam, 0).
//
// R3: wave-exact schedule. n4 = 1,572,864 float4 = 1024 blocks * 256 threads
// * 6 iters exactly. 1024 blocks <= 1184 concurrent (8/SM @ 256thr) -> ONE
// wave, no ragged tail (R2's regression), no bounds checks, 6 independent
// batched float4 loads per thread (MLP=6).

constexpr int THREADS = 256;
constexpr int EXACT_BLOCKS = 1024;
constexpr int EXACT_UNROLL = 6;

__global__ void deq_st_exact(const float4* __restrict__ x,
                             const float* __restrict__ lam_ptr,
                             float4* __restrict__ out) {
    // Grid-stride layout with compile-time trip count: stride = grid span.
    const int stride = EXACT_BLOCKS * THREADS;           // 262144
    int base = blockIdx.x * THREADS + threadIdx.x;

    const float lam = *lam_ptr;

    float4 v[EXACT_UNROLL];
#pragma unroll
    for (int j = 0; j < EXACT_UNROLL; j++)
        v[j] = x[base + j * stride];                     // 6 independent loads

#pragma unroll
    for (int j = 0; j < EXACT_UNROLL; j++) {
        float4 r;
        r.x = copysignf(fmaxf(fabsf(v[j].x) - lam, 0.0f), v[j].x);
        r.y = copysignf(fmaxf(fabsf(v[j].y) - lam, 0.0f), v[j].y);
        r.z = copysignf(fmaxf(fabsf(v[j].z) - lam, 0.0f), v[j].z);
        r.w = copysignf(fmaxf(fabsf(v[j].w) - lam, 0.0f), v[j].w);
        out[base + j * stride] = r;
    }
}

// Generic fallback for shapes that don't divide exactly (not used for this
// problem's 8*3*512*512, but keeps the kernel correct for any n).
__global__ void deq_st_generic(const float* __restrict__ x,
                               const float* __restrict__ lam_ptr,
                               float* __restrict__ out, int n) {
    const float lam = *lam_ptr;
    for (int i = blockIdx.x * blockDim.x + threadIdx.x; i < n;
         i += gridDim.x * blockDim.x) {
        float v = x[i];
        out[i] = copysignf(fmaxf(fabsf(v) - lam, 0.0f), v);
    }
}

extern "C" void kernel_launch(void* const* d_in, const int* in_sizes, int n_in,
                              void* d_out, int out_size) {
    const float* x0  = (const float*)d_in[0];
    const float* lam = (const float*)d_in[2];   // d_in[1]=rho irrelevant to fixed point
    float* out = (float*)d_out;

    int n  = in_sizes[0];
    int n4 = n >> 2;

    if ((n & 3) == 0 && n4 == EXACT_BLOCKS * THREADS * EXACT_UNROLL) {
        deq_st_exact<<<EXACT_BLOCKS, THREADS>>>(
            (const float4*)x0, lam, (float4*)out);
    } else {
        int blocks = 1184;                       // ~one full wave of the chip
        deq_st_generic<<<blocks, THREADS>>>(x0, lam, out, n);
    }
}